// round 13
// baseline (speedup 1.0000x reference)
#include <cuda_runtime.h>
#include <cuda_fp16.h>
#include <stdint.h>
#include <math.h>

#define N_BANDS 15
#define BW_     129
#define HOP_    64
#define NFREQ   1025
#define EMB     128
#define MLPD    512
#define TLEN    2048
#define TM      128
#define NTH     512
#define W2ROWS  1032
#define W2PAD   1056
#define NCH2    33

// smem layout (bytes) — 80KB total, 1 CTA/SM (RF-capped anyway)
#define AQN_OFF   0          // GEMM1: qn [128][256B] = 32768
#define W1STG_OFF 32768      // GEMM1: 2 x 16384
#define W2STG_OFF 0          // GEMM2: 2 x 32768 (aliases qn + W1 staging)
#define CMB_OFF   65536      // K-combine 16KB
#define SMEM_TOTAL 81920

__device__ __align__(16) __half g_W1T[(size_t)N_BANDS * MLPD * EMB];
__device__ __align__(16) __half g_W2T[(size_t)N_BANDS * W2PAD * MLPD];
__device__ float g_b2i[N_BANDS * W2ROWS];
__device__ float g_scr[(size_t)2 * N_BANDS * 516 * TLEN];

__device__ __forceinline__ uint32_t smem_u32(const void* p){
    uint32_t a;
    asm("{ .reg .u64 t; cvta.to.shared.u64 t, %1; cvt.u32.u64 %0, t; }" : "=r"(a) : "l"(p));
    return a;
}
__device__ __forceinline__ void ldsm4(uint32_t* r, uint32_t a){
    asm volatile("ldmatrix.sync.aligned.m8n8.x4.shared.b16 {%0,%1,%2,%3}, [%4];"
        : "=r"(r[0]),"=r"(r[1]),"=r"(r[2]),"=r"(r[3]) : "r"(a));
}
__device__ __forceinline__ void mma16816(float* c, const uint32_t* a, uint32_t b0, uint32_t b1){
    asm volatile("mma.sync.aligned.m16n8k16.row.col.f32.f16.f16.f32 "
        "{%0,%1,%2,%3}, {%4,%5,%6,%7}, {%8,%9}, {%0,%1,%2,%3};"
        : "+f"(c[0]),"+f"(c[1]),"+f"(c[2]),"+f"(c[3])
        : "r"(a[0]),"r"(a[1]),"r"(a[2]),"r"(a[3]),"r"(b0),"r"(b1));
}
__device__ __forceinline__ uint32_t f2h2(float a, float b){
    __half2 h = __floats2half2_rn(a, b);
    return *(uint32_t*)&h;
}
__device__ __forceinline__ void cpa16(uint32_t dst, const void* src){
    asm volatile("cp.async.cg.shared.global [%0], [%1], 16;" :: "r"(dst), "l"(src));
}
__device__ __forceinline__ void cpa_commit(){ asm volatile("cp.async.commit_group;" ::: "memory"); }
__device__ __forceinline__ void cpa_wait0(){ asm volatile("cp.async.wait_group 0;" ::: "memory"); }

__device__ __forceinline__ float tanh_fast(float x){
    x = fminf(fmaxf(x, -15.f), 15.f);
    float e = __expf(2.0f * x);
    return __fdividef(e - 1.0f, e + 1.0f);
}
__device__ __forceinline__ float sigm_fast(float g){
    return __fdividef(1.0f, 1.0f + __expf(-g));
}

// ---------------- prep kernels ----------------
__global__ void prep_b2i(const float* __restrict__ b2, const float* __restrict__ fw){
    int idx = blockIdx.x * blockDim.x + threadIdx.x;
    if (idx >= N_BANDS * W2ROWS) return;
    int r = idx % W2ROWS, n = idx / W2ROWS;
    int j = r >> 1, gbit = r & 1;
    float v = b2[(size_t)n * W2ROWS + (gbit ? j + 516 : j)];
    if (!gbit){
        int cc = j >= 258; int rem = j - cc * 258;
        v *= fw[n * BW_ + (rem >> 1)];
    }
    g_b2i[idx] = v;
}

__global__ void prep_w1_t(const float* __restrict__ W1){
    __shared__ float s[64][65];
    const int n = blockIdx.z, f0 = blockIdx.y * 64, e0 = blockIdx.x * 64;
    const int tid = threadIdx.x;
    const int i0 = tid >> 6, j = tid & 63;
    const float* src = W1 + ((size_t)n * EMB + e0) * MLPD + f0;
    #pragma unroll
    for (int p = 0; p < 16; p++){
        int i = p * 4 + i0;
        s[i][j] = src[(size_t)i * MLPD + j];
    }
    __syncthreads();
    __half* dst = g_W1T + ((size_t)n * MLPD + f0) * EMB + e0;
    #pragma unroll
    for (int p = 0; p < 16; p++){
        int jj = p * 4 + i0;
        dst[(size_t)jj * EMB + j] = __float2half(s[j][jj]);
    }
}

__global__ void prep_w2_t(const float* __restrict__ W2, const float* __restrict__ fw){
    __shared__ float sa[64][33], sg[64][33];
    const int n = blockIdx.z, j0 = blockIdx.y * 32, k0 = blockIdx.x * 64;
    const int tid = threadIdx.x;
    const int kk0 = tid >> 5, jj = tid & 31;
    const float* src = W2 + (size_t)n * MLPD * W2ROWS + (size_t)k0 * W2ROWS;
    const int jf_l = j0 + jj;
    #pragma unroll
    for (int p = 0; p < 8; p++){
        int kk = p * 8 + kk0;
        float va = 0.f, vg = 0.f;
        if (jf_l < 516){
            va = src[(size_t)kk * W2ROWS + jf_l];
            vg = src[(size_t)kk * W2ROWS + 516 + jf_l];
        }
        sa[kk][jj] = va; sg[kk][jj] = vg;
    }
    __syncthreads();
    const int w = tid >> 5, kk2 = tid & 31;
    #pragma unroll
    for (int p = 0; p < 8; p++){
        int rl = p * 8 + w;
        int jj2 = rl >> 1, g = rl & 1;
        int jf = j0 + jj2;
        int r = 2 * jf + g;
        if (r < W2PAD){
            float v0, v1;
            if (g){ v0 = sg[2*kk2][jj2]; v1 = sg[2*kk2+1][jj2]; }
            else {
                v0 = sa[2*kk2][jj2]; v1 = sa[2*kk2+1][jj2];
                if (jf < 516){
                    int cc = jf >= 258; int rem = jf - cc * 258;
                    float fwv = fw[n * BW_ + (rem >> 1)];
                    v0 *= fwv; v1 *= fwv;
                }
            }
            *(__half2*)(g_W2T + ((size_t)n * W2PAD + r) * MLPD + k0 + 2 * kk2) =
                __floats2half2_rn(v0, v1);
        }
    }
}

// ---------------- gather ----------------
__global__ void gather_kernel(float* __restrict__ out, int B){
    int idx = blockIdx.x * blockDim.x + threadIdx.x;
    int total = B * 2 * NFREQ * TLEN;
    if (idx >= total) return;
    int t    = idx & (TLEN - 1);
    int rest = idx >> 11;
    int freq = rest % NFREQ;
    int rest2 = rest / NFREQ;
    int c = rest2 & 1;
    int b = rest2 >> 1;
    int n_lo = (freq >= 128) ? ((freq - 128 + 63) >> 6) : 0;
    int n_hi = freq >> 6; if (n_hi > 14) n_hi = 14;
    float s0 = 0.f, s1 = 0.f;
    for (int n = n_lo; n <= n_hi; n++){
        int f = freq - (n << 6);
        const float* base = g_scr + (((size_t)(b * N_BANDS + n) * 516) + (size_t)(c * 258 + 2 * f)) * TLEN + t;
        s0 += base[0];
        s1 += base[TLEN];
    }
    float2 v; v.x = s0; v.y = s1;
    ((float2*)out)[idx] = v;
}

// ---------------- main kernel ----------------
__global__ __launch_bounds__(NTH, 1)
void omem_hmma_kernel(const float* __restrict__ q,
                      const float* __restrict__ ln_gamma,
                      const float* __restrict__ ln_beta,
                      const float* __restrict__ b1){
    extern __shared__ __align__(1024) char smem[];
    const uint32_t sb = smem_u32(smem);
    const int tid = threadIdx.x, warp = tid >> 5, lane = tid & 31;
    const int wm = warp & 7, whi = warp >> 3;  // 8 M-warps x 2 K-halves
    const int b = blockIdx.z, n = blockIdx.y, t0 = blockIdx.x * TM;

    const __half* W1Tn = g_W1T + (size_t)n * MLPD * EMB;

    // prefetch W1 feature-chunk 0 before LN (64 rows x 256B = 16KB, 2/thread)
    {
        #pragma unroll
        for (int i = 0; i < 2; i++){
            int lin = i * NTH + tid; int rl = lin >> 4, cn = lin & 15;
            int grow = (rl < 32) ? rl : 256 + (rl - 32);
            cpa16(sb + W1STG_OFF + rl * 256 + (((uint32_t)cn ^ (rl & 7)) << 4),
                  W1Tn + (size_t)grow * EMB + cn * 8);
        }
        cpa_commit();
    }

    // ---- LayerNorm -> qn fp16, swizzled [128][256B] ----
    {
        const float* qb = q + ((size_t)(b * N_BANDS + n) * TLEN + t0) * EMB;
        float4 gg  = ((const float4*)(ln_gamma + (size_t)n * EMB))[lane];
        float4 bet = ((const float4*)(ln_beta  + (size_t)n * EMB))[lane];
        for (int i = warp; i < TM; i += 16){
            float4 v = ((const float4*)(qb + (size_t)i * EMB))[lane];
            float s  = v.x + v.y + v.z + v.w;
            float s2 = v.x*v.x + v.y*v.y + v.z*v.z + v.w*v.w;
            #pragma unroll
            for (int off = 16; off; off >>= 1){
                s  += __shfl_xor_sync(0xffffffffu, s,  off);
                s2 += __shfl_xor_sync(0xffffffffu, s2, off);
            }
            float mu = s * (1.0f/EMB);
            float var = s2 * (1.0f/EMB) - mu*mu;
            float rs = rsqrtf(var + 1e-5f);
            uint2 pk;
            pk.x = f2h2((v.x - mu)*rs*gg.x + bet.x, (v.y - mu)*rs*gg.y + bet.y);
            pk.y = f2h2((v.z - mu)*rs*gg.z + bet.z, (v.w - mu)*rs*gg.w + bet.w);
            uint32_t ch = (uint32_t)(lane >> 1) ^ (uint32_t)(i & 7);
            *(uint2*)(smem + AQN_OFF + i * 256 + ch * 16 + (lane & 1) * 8) = pk;
        }
    }

    const uint32_t aRow = wm * 16 + (lane & 15);
    const uint32_t aS   = aRow & 7;
    const uint32_t aHi  = lane >> 4;
    const uint32_t bRowL = (lane & 7) | ((lane & 16) >> 1);
    const uint32_t bHi   = (lane >> 3) & 1;
    const uint32_t bS    = bRowL & 7;

    uint32_t aOff[4], bOff[4];
    #pragma unroll
    for (int j2 = 0; j2 < 4; j2++){
        aOff[j2] = (((2u*j2 + aHi) ^ aS) << 4);
        bOff[j2] = (((2u*j2 + bHi) ^ bS) << 4);
    }

    cpa_wait0();
    __syncthreads();

    uint32_t afr[16][4];

    // ---- GEMM1 (fused): 16 token-rows x 256 features per warp ----
    {
        const float* b1n = b1 + (size_t)n * MLPD;
        uint32_t aA[4];
        #pragma unroll
        for (int j2 = 0; j2 < 4; j2++) aA[j2] = sb + AQN_OFF + aRow * 256 + aOff[j2];
        #pragma unroll 1
        for (int c = 0; c < 8; c++){
            const int cbuf = c & 1, nbuf = (c + 1) & 1;
            float acc[4][4];
            #pragma unroll
            for (int t = 0; t < 4; t++){ acc[t][0]=0.f; acc[t][1]=0.f; acc[t][2]=0.f; acc[t][3]=0.f; }
            uint32_t bB[4];
            #pragma unroll
            for (int j2 = 0; j2 < 4; j2++)
                bB[j2] = sb + W1STG_OFF + cbuf * 16384 + (whi * 32 + bRowL) * 256 + bOff[j2];
            #pragma unroll
            for (int ks = 0; ks < 8; ks++){
                uint32_t ko = (uint32_t)(ks >> 2) * 128u;
                uint32_t a[4], br0[4], br1[4];
                ldsm4(a,   aA[ks & 3] + ko);
                ldsm4(br0, bB[ks & 3] + ko);
                ldsm4(br1, bB[ks & 3] + ko + 16 * 256);
                mma16816(acc[0], a, br0[0], br0[1]);
                mma16816(acc[1], a, br0[2], br0[3]);
                mma16816(acc[2], a, br1[0], br1[1]);
                mma16816(acc[3], a, br1[2], br1[3]);
            }
            if (c + 1 < 8){
                #pragma unroll
                for (int i = 0; i < 2; i++){
                    int lin = i * NTH + tid; int rl = lin >> 4, cn = lin & 15;
                    int grow = (rl < 32) ? (c + 1) * 32 + rl : 256 + (c + 1) * 32 + (rl - 32);
                    cpa16(sb + W1STG_OFF + nbuf * 16384 + rl * 256 + (((uint32_t)cn ^ (rl & 7)) << 4),
                          W1Tn + (size_t)grow * EMB + cn * 8);
                }
                cpa_commit();
            }
            const int fbase = whi * 256 + c * 32;
            #pragma unroll
            for (int t = 0; t < 4; t++){
                int ng = fbase + t * 8 + 2 * (lane & 3);
                float2 bb = *(const float2*)(b1n + ng);
                float v0 = tanh_fast(acc[t][0] + bb.x);
                float v1 = tanh_fast(acc[t][1] + bb.y);
                float v2 = tanh_fast(acc[t][2] + bb.x);
                float v3 = tanh_fast(acc[t][3] + bb.y);
                afr[2*c + (t >> 1)][(t & 1) * 2 + 0] = f2h2(v0, v1);
                afr[2*c + (t >> 1)][(t & 1) * 2 + 1] = f2h2(v2, v3);
            }
            if (c + 1 < 8) cpa_wait0();
            __syncthreads();
        }
    }

    // ---- GEMM2: o = h @ W2T^T (M=128,K=512,Npad=1056), double-buffered B ----
    {
        const __half* W2Tn = g_W2T + (size_t)n * W2PAD * MLPD;
        const float*  b2in = g_b2i + n * W2ROWS;

        uint32_t bA0[4], bA1[4];
        #pragma unroll
        for (int j2 = 0; j2 < 4; j2++){
            uint32_t base = sb + W2STG_OFF + bRowL * 1024 + bOff[j2] + (uint32_t)whi * 512u;
            bA0[j2] = base;
            bA1[j2] = base + 16 * 1024;
        }

        // preload chunk 0 into buf 0 (32KB = 4/thread)
        {
            #pragma unroll
            for (int i = 0; i < 4; i++){
                int lin = i * NTH + tid; int r = lin >> 6, cn = lin & 63;
                cpa16(sb + W2STG_OFF + r * 1024 + (((uint32_t)cn ^ (r & 7)) << 4),
                      W2Tn + (size_t)r * MLPD + cn * 8);
            }
            cpa_commit();
            cpa_wait0();
        }
        __syncthreads();

        const size_t scrb = (size_t)(b * N_BANDS + n) * 516;
        const int tok0 = t0 + wm * 16 + (lane >> 2);
        const uint32_t cmb = CMB_OFF + (uint32_t)wm * 2048u + (uint32_t)lane * 16u;

        #pragma unroll 1
        for (int c = 0; c < NCH2; c++){
            const uint32_t bufo = (uint32_t)(c & 1) * 32768u;
            float acc[4][4];
            #pragma unroll
            for (int t = 0; t < 4; t++){ acc[t][0]=0.f; acc[t][1]=0.f; acc[t][2]=0.f; acc[t][3]=0.f; }
            #pragma unroll
            for (int j = 0; j < 16; j++){
                uint32_t ko = bufo + (uint32_t)(j >> 2) * 128u;
                uint32_t br0[4], br1[4];
                ldsm4(br0, bA0[j & 3] + ko);
                ldsm4(br1, bA1[j & 3] + ko);
                mma16816(acc[0], afr[j], br0[0], br0[1]);
                mma16816(acc[1], afr[j], br0[2], br0[3]);
                mma16816(acc[2], afr[j], br1[0], br1[1]);
                mma16816(acc[3], afr[j], br1[2], br1[3]);
            }
            if (c + 1 < NCH2){
                const __half* src = W2Tn + (size_t)(c + 1) * 32 * MLPD;
                const uint32_t nbufo = (uint32_t)((c + 1) & 1) * 32768u;
                #pragma unroll
                for (int i = 0; i < 4; i++){
                    int lin = i * NTH + tid; int r = lin >> 6, cn = lin & 63;
                    cpa16(sb + W2STG_OFF + nbufo + r * 1024 + (((uint32_t)cn ^ (r & 7)) << 4),
                          src + (size_t)r * MLPD + cn * 8);
                }
                cpa_commit();
            }
            if (whi){
                #pragma unroll
                for (int t = 0; t < 4; t++){
                    float4 v; v.x = acc[t][0]; v.y = acc[t][1]; v.z = acc[t][2]; v.w = acc[t][3];
                    *(float4*)(smem + cmb + t * 512) = v;
                }
            }
            __syncthreads();
            if (!whi){
                #pragma unroll
                for (int t = 0; t < 4; t++){
                    float4 v = *(const float4*)(smem + cmb + t * 512);
                    int jp = c * 16 + t * 4 + (lane & 3);
                    if (jp < 516){
                        float2 bb = *(const float2*)(b2in + 2 * jp);
                        float a0 = acc[t][0] + v.x + bb.x, g0 = acc[t][1] + v.y + bb.y;
                        float a1 = acc[t][2] + v.z + bb.x, g1 = acc[t][3] + v.w + bb.y;
                        float* dst = g_scr + (scrb + (size_t)jp) * TLEN + tok0;
                        dst[0] = a0 * sigm_fast(g0);
                        dst[8] = a1 * sigm_fast(g1);
                    }
                }
            }
            if (c + 1 < NCH2) cpa_wait0();
            __syncthreads();
        }
    }
}

extern "C" void kernel_launch(void* const* d_in, const int* in_sizes, int n_in,
                              void* d_out, int out_size){
    const float* q        = (const float*)d_in[0];
    const float* ln_gamma = (const float*)d_in[1];
    const float* ln_beta  = (const float*)d_in[2];
    const float* W1       = (const float*)d_in[3];
    const float* b1       = (const float*)d_in[4];
    const float* W2       = (const float*)d_in[5];
    const float* b2       = (const float*)d_in[6];
    const float* fw       = (const float*)d_in[7];
    float* out = (float*)d_out;

    int B = in_sizes[0] / (N_BANDS * TLEN * EMB);

    prep_b2i<<<(N_BANDS * W2ROWS + 255) / 256, 256>>>(b2, fw);
    { dim3 g1(2, 8, N_BANDS);  prep_w1_t<<<g1, 256>>>(W1); }
    { dim3 g2(8, 17, N_BANDS); prep_w2_t<<<g2, 256>>>(W2, fw); }

    cudaFuncSetAttribute(omem_hmma_kernel, cudaFuncAttributeMaxDynamicSharedMemorySize, SMEM_TOTAL);
    dim3 grid(TLEN / TM, N_BANDS, B);
    omem_hmma_kernel<<<grid, NTH, SMEM_TOTAL>>>(q, ln_gamma, ln_beta, b1);

    {
        int total = B * 2 * NFREQ * TLEN;
        gather_kernel<<<(total + 255) / 256, 256>>>(out, B);
    }
}

// round 14
// speedup vs baseline: 1.0731x; 1.0731x over previous
#include <cuda_runtime.h>
#include <cuda_fp16.h>
#include <stdint.h>
#include <math.h>

#define N_BANDS 15
#define BW_     129
#define HOP_    64
#define NFREQ   1025
#define EMB     128
#define MLPD    512
#define TLEN    2048
#define TM      64
#define NTH     256
#define W2ROWS  1032
#define W2PAD   1056
#define NCH2    33

// smem layout (bytes) — 80KB total -> 2 CTAs/SM
#define AQN_OFF   0          // GEMM1: qn [64][256B] = 16384
#define W1STG_OFF 16384      // GEMM1: 2 x 16384
#define W2STG_OFF 0          // GEMM2: 2 x 32768 (aliases qn + W1 staging)
#define CMB_OFF   65536      // K-combine, double buffered 2 x 8192
#define SMEM_TOTAL 81920

__device__ __align__(16) __half g_W1T[(size_t)N_BANDS * MLPD * EMB];
__device__ __align__(16) __half g_W2T[(size_t)N_BANDS * W2PAD * MLPD];
__device__ float g_b2i[N_BANDS * W2ROWS];
__device__ float g_scr[(size_t)2 * N_BANDS * 516 * TLEN];

__device__ __forceinline__ uint32_t smem_u32(const void* p){
    uint32_t a;
    asm("{ .reg .u64 t; cvta.to.shared.u64 t, %1; cvt.u32.u64 %0, t; }" : "=r"(a) : "l"(p));
    return a;
}
__device__ __forceinline__ void ldsm4(uint32_t* r, uint32_t a){
    asm volatile("ldmatrix.sync.aligned.m8n8.x4.shared.b16 {%0,%1,%2,%3}, [%4];"
        : "=r"(r[0]),"=r"(r[1]),"=r"(r[2]),"=r"(r[3]) : "r"(a));
}
__device__ __forceinline__ void mma16816(float* c, const uint32_t* a, uint32_t b0, uint32_t b1){
    asm volatile("mma.sync.aligned.m16n8k16.row.col.f32.f16.f16.f32 "
        "{%0,%1,%2,%3}, {%4,%5,%6,%7}, {%8,%9}, {%0,%1,%2,%3};"
        : "+f"(c[0]),"+f"(c[1]),"+f"(c[2]),"+f"(c[3])
        : "r"(a[0]),"r"(a[1]),"r"(a[2]),"r"(a[3]),"r"(b0),"r"(b1));
}
__device__ __forceinline__ uint32_t f2h2(float a, float b){
    __half2 h = __floats2half2_rn(a, b);
    return *(uint32_t*)&h;
}
__device__ __forceinline__ void cpa16(uint32_t dst, const void* src){
    asm volatile("cp.async.cg.shared.global [%0], [%1], 16;" :: "r"(dst), "l"(src));
}
__device__ __forceinline__ void cpa_commit(){ asm volatile("cp.async.commit_group;" ::: "memory"); }
__device__ __forceinline__ void cpa_wait0(){ asm volatile("cp.async.wait_group 0;" ::: "memory"); }

__device__ __forceinline__ float tanh_fast(float x){
    x = fminf(fmaxf(x, -15.f), 15.f);
    float e = __expf(2.0f * x);
    return __fdividef(e - 1.0f, e + 1.0f);
}
__device__ __forceinline__ float sigm_fast(float g){
    return __fdividef(1.0f, 1.0f + __expf(-g));
}

// ---------------- prep kernels ----------------
__global__ void prep_b2i(const float* __restrict__ b2, const float* __restrict__ fw){
    int idx = blockIdx.x * blockDim.x + threadIdx.x;
    if (idx >= N_BANDS * W2ROWS) return;
    int r = idx % W2ROWS, n = idx / W2ROWS;
    int j = r >> 1, gbit = r & 1;
    float v = b2[(size_t)n * W2ROWS + (gbit ? j + 516 : j)];
    if (!gbit){
        int cc = j >= 258; int rem = j - cc * 258;
        v *= fw[n * BW_ + (rem >> 1)];
    }
    g_b2i[idx] = v;
}

__global__ void prep_w1_t(const float* __restrict__ W1){
    __shared__ float s[64][65];
    const int n = blockIdx.z, f0 = blockIdx.y * 64, e0 = blockIdx.x * 64;
    const int tid = threadIdx.x;
    const int i0 = tid >> 6, j = tid & 63;
    const float* src = W1 + ((size_t)n * EMB + e0) * MLPD + f0;
    #pragma unroll
    for (int p = 0; p < 16; p++){
        int i = p * 4 + i0;
        s[i][j] = src[(size_t)i * MLPD + j];
    }
    __syncthreads();
    __half* dst = g_W1T + ((size_t)n * MLPD + f0) * EMB + e0;
    #pragma unroll
    for (int p = 0; p < 16; p++){
        int jj = p * 4 + i0;
        dst[(size_t)jj * EMB + j] = __float2half(s[j][jj]);
    }
}

__global__ void prep_w2_t(const float* __restrict__ W2, const float* __restrict__ fw){
    __shared__ float sa[64][33], sg[64][33];
    const int n = blockIdx.z, j0 = blockIdx.y * 32, k0 = blockIdx.x * 64;
    const int tid = threadIdx.x;
    const int kk0 = tid >> 5, jj = tid & 31;
    const float* src = W2 + (size_t)n * MLPD * W2ROWS + (size_t)k0 * W2ROWS;
    const int jf_l = j0 + jj;
    #pragma unroll
    for (int p = 0; p < 8; p++){
        int kk = p * 8 + kk0;
        float va = 0.f, vg = 0.f;
        if (jf_l < 516){
            va = src[(size_t)kk * W2ROWS + jf_l];
            vg = src[(size_t)kk * W2ROWS + 516 + jf_l];
        }
        sa[kk][jj] = va; sg[kk][jj] = vg;
    }
    __syncthreads();
    const int w = tid >> 5, kk2 = tid & 31;
    #pragma unroll
    for (int p = 0; p < 8; p++){
        int rl = p * 8 + w;
        int jj2 = rl >> 1, g = rl & 1;
        int jf = j0 + jj2;
        int r = 2 * jf + g;
        if (r < W2PAD){
            float v0, v1;
            if (g){ v0 = sg[2*kk2][jj2]; v1 = sg[2*kk2+1][jj2]; }
            else {
                v0 = sa[2*kk2][jj2]; v1 = sa[2*kk2+1][jj2];
                if (jf < 516){
                    int cc = jf >= 258; int rem = jf - cc * 258;
                    float fwv = fw[n * BW_ + (rem >> 1)];
                    v0 *= fwv; v1 *= fwv;
                }
            }
            *(__half2*)(g_W2T + ((size_t)n * W2PAD + r) * MLPD + k0 + 2 * kk2) =
                __floats2half2_rn(v0, v1);
        }
    }
}

// ---------------- gather ----------------
__global__ void gather_kernel(float* __restrict__ out, int B){
    int idx = blockIdx.x * blockDim.x + threadIdx.x;
    int total = B * 2 * NFREQ * TLEN;
    if (idx >= total) return;
    int t    = idx & (TLEN - 1);
    int rest = idx >> 11;
    int freq = rest % NFREQ;
    int rest2 = rest / NFREQ;
    int c = rest2 & 1;
    int b = rest2 >> 1;
    int n_lo = (freq >= 128) ? ((freq - 128 + 63) >> 6) : 0;
    int n_hi = freq >> 6; if (n_hi > 14) n_hi = 14;
    float s0 = 0.f, s1 = 0.f;
    for (int n = n_lo; n <= n_hi; n++){
        int f = freq - (n << 6);
        const float* base = g_scr + (((size_t)(b * N_BANDS + n) * 516) + (size_t)(c * 258 + 2 * f)) * TLEN + t;
        s0 += base[0];
        s1 += base[TLEN];
    }
    float2 v; v.x = s0; v.y = s1;
    ((float2*)out)[idx] = v;
}

// ---------------- main kernel ----------------
__global__ __launch_bounds__(NTH, 2)
void omem_hmma_kernel(const float* __restrict__ q,
                      const float* __restrict__ ln_gamma,
                      const float* __restrict__ ln_beta,
                      const float* __restrict__ b1){
    extern __shared__ __align__(1024) char smem[];
    const uint32_t sb = smem_u32(smem);
    const int tid = threadIdx.x, warp = tid >> 5, lane = tid & 31;
    const int wm = warp & 3, whi = warp >> 2;
    const int b = blockIdx.z, n = blockIdx.y, t0 = blockIdx.x * TM;

    const __half* W1Tn = g_W1T + (size_t)n * MLPD * EMB;

    // prefetch W1 feature-chunk 0 before LN
    {
        #pragma unroll
        for (int i = 0; i < 4; i++){
            int lin = i * NTH + tid; int rl = lin >> 4, cn = lin & 15;
            int grow = (rl < 32) ? rl : 256 + (rl - 32);
            cpa16(sb + W1STG_OFF + rl * 256 + (((uint32_t)cn ^ (rl & 7)) << 4),
                  W1Tn + (size_t)grow * EMB + cn * 8);
        }
        cpa_commit();
    }

    // ---- LayerNorm -> qn fp16, swizzled [64][256B] ----
    {
        const float* qb = q + ((size_t)(b * N_BANDS + n) * TLEN + t0) * EMB;
        float4 gg  = ((const float4*)(ln_gamma + (size_t)n * EMB))[lane];
        float4 bet = ((const float4*)(ln_beta  + (size_t)n * EMB))[lane];
        for (int i = warp; i < TM; i += 8){
            float4 v = ((const float4*)(qb + (size_t)i * EMB))[lane];
            float s  = v.x + v.y + v.z + v.w;
            float s2 = v.x*v.x + v.y*v.y + v.z*v.z + v.w*v.w;
            #pragma unroll
            for (int off = 16; off; off >>= 1){
                s  += __shfl_xor_sync(0xffffffffu, s,  off);
                s2 += __shfl_xor_sync(0xffffffffu, s2, off);
            }
            float mu = s * (1.0f/EMB);
            float var = s2 * (1.0f/EMB) - mu*mu;
            float rs = rsqrtf(var + 1e-5f);
            uint2 pk;
            pk.x = f2h2((v.x - mu)*rs*gg.x + bet.x, (v.y - mu)*rs*gg.y + bet.y);
            pk.y = f2h2((v.z - mu)*rs*gg.z + bet.z, (v.w - mu)*rs*gg.w + bet.w);
            uint32_t ch = (uint32_t)(lane >> 1) ^ (uint32_t)(i & 7);
            *(uint2*)(smem + AQN_OFF + i * 256 + ch * 16 + (lane & 1) * 8) = pk;
        }
    }

    const uint32_t aRow = wm * 16 + (lane & 15);
    const uint32_t aS   = aRow & 7;
    const uint32_t aHi  = lane >> 4;
    const uint32_t bRowL = (lane & 7) | ((lane & 16) >> 1);
    const uint32_t bHi   = (lane >> 3) & 1;
    const uint32_t bS    = bRowL & 7;

    uint32_t aOff[4], bOff[4];
    #pragma unroll
    for (int j2 = 0; j2 < 4; j2++){
        aOff[j2] = (((2u*j2 + aHi) ^ aS) << 4);
        bOff[j2] = (((2u*j2 + bHi) ^ bS) << 4);
    }

    cpa_wait0();
    __syncthreads();

    uint32_t afr[16][4];

    // ---- GEMM1 (fused): 16 token-rows x 256 features per warp ----
    {
        const float* b1n = b1 + (size_t)n * MLPD;
        uint32_t aA[4];
        #pragma unroll
        for (int j2 = 0; j2 < 4; j2++) aA[j2] = sb + AQN_OFF + aRow * 256 + aOff[j2];
        #pragma unroll 1
        for (int c = 0; c < 8; c++){
            const int cbuf = c & 1, nbuf = (c + 1) & 1;
            float acc[4][4];
            #pragma unroll
            for (int t = 0; t < 4; t++){ acc[t][0]=0.f; acc[t][1]=0.f; acc[t][2]=0.f; acc[t][3]=0.f; }
            uint32_t bB[4];
            #pragma unroll
            for (int j2 = 0; j2 < 4; j2++)
                bB[j2] = sb + W1STG_OFF + cbuf * 16384 + (whi * 32 + bRowL) * 256 + bOff[j2];
            #pragma unroll
            for (int ks = 0; ks < 8; ks++){
                uint32_t ko = (uint32_t)(ks >> 2) * 128u;
                uint32_t a[4], br0[4], br1[4];
                ldsm4(a,   aA[ks & 3] + ko);
                ldsm4(br0, bB[ks & 3] + ko);
                ldsm4(br1, bB[ks & 3] + ko + 16 * 256);
                mma16816(acc[0], a, br0[0], br0[1]);
                mma16816(acc[1], a, br0[2], br0[3]);
                mma16816(acc[2], a, br1[0], br1[1]);
                mma16816(acc[3], a, br1[2], br1[3]);
            }
            if (c + 1 < 8){
                #pragma unroll
                for (int i = 0; i < 4; i++){
                    int lin = i * NTH + tid; int rl = lin >> 4, cn = lin & 15;
                    int grow = (rl < 32) ? (c + 1) * 32 + rl : 256 + (c + 1) * 32 + (rl - 32);
                    cpa16(sb + W1STG_OFF + nbuf * 16384 + rl * 256 + (((uint32_t)cn ^ (rl & 7)) << 4),
                          W1Tn + (size_t)grow * EMB + cn * 8);
                }
                cpa_commit();
            }
            const int fbase = whi * 256 + c * 32;
            #pragma unroll
            for (int t = 0; t < 4; t++){
                int ng = fbase + t * 8 + 2 * (lane & 3);
                float2 bb = *(const float2*)(b1n + ng);
                float v0 = tanh_fast(acc[t][0] + bb.x);
                float v1 = tanh_fast(acc[t][1] + bb.y);
                float v2 = tanh_fast(acc[t][2] + bb.x);
                float v3 = tanh_fast(acc[t][3] + bb.y);
                afr[2*c + (t >> 1)][(t & 1) * 2 + 0] = f2h2(v0, v1);
                afr[2*c + (t >> 1)][(t & 1) * 2 + 1] = f2h2(v2, v3);
            }
            if (c + 1 < 8) cpa_wait0();
            __syncthreads();
        }
    }

    // ---- GEMM2: o = h @ W2T^T, double-buffered B + double-buffered combine,
    //      ONE barrier per chunk, symmetric epilogue split ----
    {
        const __half* W2Tn = g_W2T + (size_t)n * W2PAD * MLPD;
        const float*  b2in = g_b2i + n * W2ROWS;

        uint32_t bA0[4], bA1[4];
        #pragma unroll
        for (int j2 = 0; j2 < 4; j2++){
            uint32_t base = sb + W2STG_OFF + bRowL * 1024 + bOff[j2] + (uint32_t)whi * 512u;
            bA0[j2] = base;
            bA1[j2] = base + 16 * 1024;
        }

        // preload chunk 0 into buf 0
        {
            #pragma unroll
            for (int i = 0; i < 8; i++){
                int lin = i * NTH + tid; int r = lin >> 6, cn = lin & 63;
                cpa16(sb + W2STG_OFF + r * 1024 + (((uint32_t)cn ^ (r & 7)) << 4),
                      W2Tn + (size_t)r * MLPD + cn * 8);
            }
            cpa_commit();
            cpa_wait0();
        }
        __syncthreads();

        const size_t scrb = (size_t)(b * N_BANDS + n) * 516;
        const int tok0 = t0 + wm * 16 + (lane >> 2);
        // combine slots: [buf(c&1)][wm][side(whi)][tile(2)][lane] float4
        const uint32_t cmbSt = CMB_OFF + (uint32_t)wm * 2048u + (uint32_t)whi * 1024u + (uint32_t)lane * 16u;
        const uint32_t cmbLd = CMB_OFF + (uint32_t)wm * 2048u + (uint32_t)(whi ^ 1) * 1024u + (uint32_t)lane * 16u;
        const int tOwn = whi * 2;     // tiles this warp epilogues
        const int tSt  = 2 - tOwn;    // tiles this warp publishes (partner's)

        #pragma unroll 1
        for (int c = 0; c < NCH2; c++){
            const uint32_t bufo = (uint32_t)(c & 1) * 32768u;
            const uint32_t cmbo = (uint32_t)(c & 1) * 8192u;
            float acc[4][4];
            #pragma unroll
            for (int t = 0; t < 4; t++){ acc[t][0]=0.f; acc[t][1]=0.f; acc[t][2]=0.f; acc[t][3]=0.f; }
            #pragma unroll
            for (int j = 0; j < 16; j++){
                uint32_t ko = bufo + (uint32_t)(j >> 2) * 128u;
                uint32_t br0[4], br1[4];
                ldsm4(br0, bA0[j & 3] + ko);
                ldsm4(br1, bA1[j & 3] + ko);
                mma16816(acc[0], afr[j], br0[0], br0[1]);
                mma16816(acc[1], afr[j], br0[2], br0[3]);
                mma16816(acc[2], afr[j], br1[0], br1[1]);
                mma16816(acc[3], afr[j], br1[2], br1[3]);
            }
            // prefetch next W2 chunk into the other buffer
            if (c + 1 < NCH2){
                const __half* src = W2Tn + (size_t)(c + 1) * 32 * MLPD;
                const uint32_t nbufo = (uint32_t)((c + 1) & 1) * 32768u;
                #pragma unroll
                for (int i = 0; i < 8; i++){
                    int lin = i * NTH + tid; int r = lin >> 6, cn = lin & 63;
                    cpa16(sb + W2STG_OFF + nbufo + r * 1024 + (((uint32_t)cn ^ (r & 7)) << 4),
                          src + (size_t)r * MLPD + cn * 8);
                }
                cpa_commit();
            }
            // publish partner's tiles (tSt, tSt+1)
            #pragma unroll
            for (int t = 0; t < 2; t++){
                float4 v;
                v.x = acc[tSt + t][0]; v.y = acc[tSt + t][1];
                v.z = acc[tSt + t][2]; v.w = acc[tSt + t][3];
                *(float4*)(smem + cmbo + cmbSt + t * 512) = v;
            }
            if (c + 1 < NCH2) cpa_wait0();
            __syncthreads();
            // epilogue for owned tiles (both halves work)
            #pragma unroll
            for (int t = 0; t < 2; t++){
                float4 v = *(const float4*)(smem + cmbo + cmbLd + t * 512);
                int tt = tOwn + t;
                int jp = c * 16 + tt * 4 + (lane & 3);
                if (jp < 516){
                    float2 bb = *(const float2*)(b2in + 2 * jp);
                    float a0 = acc[tt][0] + v.x + bb.x, g0 = acc[tt][1] + v.y + bb.y;
                    float a1 = acc[tt][2] + v.z + bb.x, g1 = acc[tt][3] + v.w + bb.y;
                    float* dst = g_scr + (scrb + (size_t)jp) * TLEN + tok0;
                    dst[0] = a0 * sigm_fast(g0);
                    dst[8] = a1 * sigm_fast(g1);
                }
            }
        }
    }
}

extern "C" void kernel_launch(void* const* d_in, const int* in_sizes, int n_in,
                              void* d_out, int out_size){
    const float* q        = (const float*)d_in[0];
    const float* ln_gamma = (const float*)d_in[1];
    const float* ln_beta  = (const float*)d_in[2];
    const float* W1       = (const float*)d_in[3];
    const float* b1       = (const float*)d_in[4];
    const float* W2       = (const float*)d_in[5];
    const float* b2       = (const float*)d_in[6];
    const float* fw       = (const float*)d_in[7];
    float* out = (float*)d_out;

    int B = in_sizes[0] / (N_BANDS * TLEN * EMB);

    prep_b2i<<<(N_BANDS * W2ROWS + 255) / 256, 256>>>(b2, fw);
    { dim3 g1(2, 8, N_BANDS);  prep_w1_t<<<g1, 256>>>(W1); }
    { dim3 g2(8, 17, N_BANDS); prep_w2_t<<<g2, 256>>>(W2, fw); }

    cudaFuncSetAttribute(omem_hmma_kernel, cudaFuncAttributeMaxDynamicSharedMemorySize, SMEM_TOTAL);
    dim3 grid(TLEN / TM, N_BANDS, B);
    omem_hmma_kernel<<<grid, NTH, SMEM_TOTAL>>>(q, ln_gamma, ln_beta, b1);

    {
        int total = B * 2 * NFREQ * TLEN;
        gather_kernel<<<(total + 255) / 256, 256>>>(out, B);
    }
}

// round 15
// speedup vs baseline: 1.1031x; 1.0279x over previous
#include <cuda_runtime.h>
#include <cuda_fp16.h>
#include <stdint.h>
#include <math.h>

#define N_BANDS 15
#define BW_     129
#define HOP_    64
#define NFREQ   1025
#define EMB     128
#define MLPD    512
#define TLEN    2048
#define TM      64
#define NTH     256
#define W2ROWS  1032
#define W2PAD   1056
#define NCH2    33

// smem layout (bytes) — 104KB total -> 2 CTAs/SM (208KB < 228KB)
#define AQN_OFF   0          // GEMM1: qn [64][256B] = 16384
#define W1STG_OFF 16384      // GEMM1: 2 x 16384 -> [16384,49152)
#define W2STG_OFF 0          // GEMM2: 3 x 32768 -> [0,98304) (aliases qn+W1)
#define CMB_OFF   98304      // K-combine 8KB
#define SMEM_TOTAL 106496

__device__ __align__(16) __half g_W1T[(size_t)N_BANDS * MLPD * EMB];
__device__ __align__(16) __half g_W2T[(size_t)N_BANDS * W2PAD * MLPD];
__device__ float g_b2i[N_BANDS * W2ROWS];
__device__ float g_scr[(size_t)2 * N_BANDS * 516 * TLEN];

__device__ __forceinline__ uint32_t smem_u32(const void* p){
    uint32_t a;
    asm("{ .reg .u64 t; cvta.to.shared.u64 t, %1; cvt.u32.u64 %0, t; }" : "=r"(a) : "l"(p));
    return a;
}
__device__ __forceinline__ void ldsm4(uint32_t* r, uint32_t a){
    asm volatile("ldmatrix.sync.aligned.m8n8.x4.shared.b16 {%0,%1,%2,%3}, [%4];"
        : "=r"(r[0]),"=r"(r[1]),"=r"(r[2]),"=r"(r[3]) : "r"(a));
}
__device__ __forceinline__ void mma16816(float* c, const uint32_t* a, uint32_t b0, uint32_t b1){
    asm volatile("mma.sync.aligned.m16n8k16.row.col.f32.f16.f16.f32 "
        "{%0,%1,%2,%3}, {%4,%5,%6,%7}, {%8,%9}, {%0,%1,%2,%3};"
        : "+f"(c[0]),"+f"(c[1]),"+f"(c[2]),"+f"(c[3])
        : "r"(a[0]),"r"(a[1]),"r"(a[2]),"r"(a[3]),"r"(b0),"r"(b1));
}
__device__ __forceinline__ uint32_t f2h2(float a, float b){
    __half2 h = __floats2half2_rn(a, b);
    return *(uint32_t*)&h;
}
__device__ __forceinline__ void cpa16(uint32_t dst, const void* src){
    asm volatile("cp.async.cg.shared.global [%0], [%1], 16;" :: "r"(dst), "l"(src));
}
__device__ __forceinline__ void cpa_commit(){ asm volatile("cp.async.commit_group;" ::: "memory"); }
__device__ __forceinline__ void cpa_wait0(){ asm volatile("cp.async.wait_group 0;" ::: "memory"); }
__device__ __forceinline__ void cpa_wait1(){ asm volatile("cp.async.wait_group 1;" ::: "memory"); }

__device__ __forceinline__ float tanh_fast(float x){
    x = fminf(fmaxf(x, -15.f), 15.f);
    float e = __expf(2.0f * x);
    return __fdividef(e - 1.0f, e + 1.0f);
}
__device__ __forceinline__ float sigm_fast(float g){
    return __fdividef(1.0f, 1.0f + __expf(-g));
}

// ---------------- prep kernels ----------------
__global__ void prep_b2i(const float* __restrict__ b2, const float* __restrict__ fw){
    int idx = blockIdx.x * blockDim.x + threadIdx.x;
    if (idx >= N_BANDS * W2ROWS) return;
    int r = idx % W2ROWS, n = idx / W2ROWS;
    int j = r >> 1, gbit = r & 1;
    float v = b2[(size_t)n * W2ROWS + (gbit ? j + 516 : j)];
    if (!gbit){
        int cc = j >= 258; int rem = j - cc * 258;
        v *= fw[n * BW_ + (rem >> 1)];
    }
    g_b2i[idx] = v;
}

__global__ void prep_w1_t(const float* __restrict__ W1){
    __shared__ float s[64][65];
    const int n = blockIdx.z, f0 = blockIdx.y * 64, e0 = blockIdx.x * 64;
    const int tid = threadIdx.x;
    const int i0 = tid >> 6, j = tid & 63;
    const float* src = W1 + ((size_t)n * EMB + e0) * MLPD + f0;
    #pragma unroll
    for (int p = 0; p < 16; p++){
        int i = p * 4 + i0;
        s[i][j] = src[(size_t)i * MLPD + j];
    }
    __syncthreads();
    __half* dst = g_W1T + ((size_t)n * MLPD + f0) * EMB + e0;
    #pragma unroll
    for (int p = 0; p < 16; p++){
        int jj = p * 4 + i0;
        dst[(size_t)jj * EMB + j] = __float2half(s[j][jj]);
    }
}

__global__ void prep_w2_t(const float* __restrict__ W2, const float* __restrict__ fw){
    __shared__ float sa[64][33], sg[64][33];
    const int n = blockIdx.z, j0 = blockIdx.y * 32, k0 = blockIdx.x * 64;
    const int tid = threadIdx.x;
    const int kk0 = tid >> 5, jj = tid & 31;
    const float* src = W2 + (size_t)n * MLPD * W2ROWS + (size_t)k0 * W2ROWS;
    const int jf_l = j0 + jj;
    #pragma unroll
    for (int p = 0; p < 8; p++){
        int kk = p * 8 + kk0;
        float va = 0.f, vg = 0.f;
        if (jf_l < 516){
            va = src[(size_t)kk * W2ROWS + jf_l];
            vg = src[(size_t)kk * W2ROWS + 516 + jf_l];
        }
        sa[kk][jj] = va; sg[kk][jj] = vg;
    }
    __syncthreads();
    const int w = tid >> 5, kk2 = tid & 31;
    #pragma unroll
    for (int p = 0; p < 8; p++){
        int rl = p * 8 + w;
        int jj2 = rl >> 1, g = rl & 1;
        int jf = j0 + jj2;
        int r = 2 * jf + g;
        if (r < W2PAD){
            float v0, v1;
            if (g){ v0 = sg[2*kk2][jj2]; v1 = sg[2*kk2+1][jj2]; }
            else {
                v0 = sa[2*kk2][jj2]; v1 = sa[2*kk2+1][jj2];
                if (jf < 516){
                    int cc = jf >= 258; int rem = jf - cc * 258;
                    float fwv = fw[n * BW_ + (rem >> 1)];
                    v0 *= fwv; v1 *= fwv;
                }
            }
            *(__half2*)(g_W2T + ((size_t)n * W2PAD + r) * MLPD + k0 + 2 * kk2) =
                __floats2half2_rn(v0, v1);
        }
    }
}

// ---------------- gather ----------------
__global__ void gather_kernel(float* __restrict__ out, int B){
    int idx = blockIdx.x * blockDim.x + threadIdx.x;
    int total = B * 2 * NFREQ * TLEN;
    if (idx >= total) return;
    int t    = idx & (TLEN - 1);
    int rest = idx >> 11;
    int freq = rest % NFREQ;
    int rest2 = rest / NFREQ;
    int c = rest2 & 1;
    int b = rest2 >> 1;
    int n_lo = (freq >= 128) ? ((freq - 128 + 63) >> 6) : 0;
    int n_hi = freq >> 6; if (n_hi > 14) n_hi = 14;
    float s0 = 0.f, s1 = 0.f;
    for (int n = n_lo; n <= n_hi; n++){
        int f = freq - (n << 6);
        const float* base = g_scr + (((size_t)(b * N_BANDS + n) * 516) + (size_t)(c * 258 + 2 * f)) * TLEN + t;
        s0 += base[0];
        s1 += base[TLEN];
    }
    float2 v; v.x = s0; v.y = s1;
    ((float2*)out)[idx] = v;
}

// ---------------- main kernel ----------------
__global__ __launch_bounds__(NTH, 2)
void omem_hmma_kernel(const float* __restrict__ q,
                      const float* __restrict__ ln_gamma,
                      const float* __restrict__ ln_beta,
                      const float* __restrict__ b1){
    extern __shared__ __align__(1024) char smem[];
    const uint32_t sb = smem_u32(smem);
    const int tid = threadIdx.x, warp = tid >> 5, lane = tid & 31;
    const int wm = warp & 3, whi = warp >> 2;
    const int b = blockIdx.z, n = blockIdx.y, t0 = blockIdx.x * TM;

    const __half* W1Tn = g_W1T + (size_t)n * MLPD * EMB;

    // prefetch W1 feature-chunk 0 before LN
    {
        #pragma unroll
        for (int i = 0; i < 4; i++){
            int lin = i * NTH + tid; int rl = lin >> 4, cn = lin & 15;
            int grow = (rl < 32) ? rl : 256 + (rl - 32);
            cpa16(sb + W1STG_OFF + rl * 256 + (((uint32_t)cn ^ (rl & 7)) << 4),
                  W1Tn + (size_t)grow * EMB + cn * 8);
        }
        cpa_commit();
    }

    // ---- LayerNorm -> qn fp16, swizzled [64][256B] ----
    {
        const float* qb = q + ((size_t)(b * N_BANDS + n) * TLEN + t0) * EMB;
        float4 gg  = ((const float4*)(ln_gamma + (size_t)n * EMB))[lane];
        float4 bet = ((const float4*)(ln_beta  + (size_t)n * EMB))[lane];
        for (int i = warp; i < TM; i += 8){
            float4 v = ((const float4*)(qb + (size_t)i * EMB))[lane];
            float s  = v.x + v.y + v.z + v.w;
            float s2 = v.x*v.x + v.y*v.y + v.z*v.z + v.w*v.w;
            #pragma unroll
            for (int off = 16; off; off >>= 1){
                s  += __shfl_xor_sync(0xffffffffu, s,  off);
                s2 += __shfl_xor_sync(0xffffffffu, s2, off);
            }
            float mu = s * (1.0f/EMB);
            float var = s2 * (1.0f/EMB) - mu*mu;
            float rs = rsqrtf(var + 1e-5f);
            uint2 pk;
            pk.x = f2h2((v.x - mu)*rs*gg.x + bet.x, (v.y - mu)*rs*gg.y + bet.y);
            pk.y = f2h2((v.z - mu)*rs*gg.z + bet.z, (v.w - mu)*rs*gg.w + bet.w);
            uint32_t ch = (uint32_t)(lane >> 1) ^ (uint32_t)(i & 7);
            *(uint2*)(smem + AQN_OFF + i * 256 + ch * 16 + (lane & 1) * 8) = pk;
        }
    }

    const uint32_t aRow = wm * 16 + (lane & 15);
    const uint32_t aS   = aRow & 7;
    const uint32_t aHi  = lane >> 4;
    const uint32_t bRowL = (lane & 7) | ((lane & 16) >> 1);
    const uint32_t bHi   = (lane >> 3) & 1;
    const uint32_t bS    = bRowL & 7;

    uint32_t aOff[4], bOff[4];
    #pragma unroll
    for (int j2 = 0; j2 < 4; j2++){
        aOff[j2] = (((2u*j2 + aHi) ^ aS) << 4);
        bOff[j2] = (((2u*j2 + bHi) ^ bS) << 4);
    }

    cpa_wait0();
    __syncthreads();

    uint32_t afr[16][4];

    // ---- GEMM1 (fused): 16 token-rows x 256 features per warp ----
    {
        const float* b1n = b1 + (size_t)n * MLPD;
        uint32_t aA[4];
        #pragma unroll
        for (int j2 = 0; j2 < 4; j2++) aA[j2] = sb + AQN_OFF + aRow * 256 + aOff[j2];
        #pragma unroll 1
        for (int c = 0; c < 8; c++){
            const int cbuf = c & 1, nbuf = (c + 1) & 1;
            float acc[4][4];
            #pragma unroll
            for (int t = 0; t < 4; t++){ acc[t][0]=0.f; acc[t][1]=0.f; acc[t][2]=0.f; acc[t][3]=0.f; }
            uint32_t bB[4];
            #pragma unroll
            for (int j2 = 0; j2 < 4; j2++)
                bB[j2] = sb + W1STG_OFF + cbuf * 16384 + (whi * 32 + bRowL) * 256 + bOff[j2];
            #pragma unroll
            for (int ks = 0; ks < 8; ks++){
                uint32_t ko = (uint32_t)(ks >> 2) * 128u;
                uint32_t a[4], br0[4], br1[4];
                ldsm4(a,   aA[ks & 3] + ko);
                ldsm4(br0, bB[ks & 3] + ko);
                ldsm4(br1, bB[ks & 3] + ko + 16 * 256);
                mma16816(acc[0], a, br0[0], br0[1]);
                mma16816(acc[1], a, br0[2], br0[3]);
                mma16816(acc[2], a, br1[0], br1[1]);
                mma16816(acc[3], a, br1[2], br1[3]);
            }
            if (c + 1 < 8){
                #pragma unroll
                for (int i = 0; i < 4; i++){
                    int lin = i * NTH + tid; int rl = lin >> 4, cn = lin & 15;
                    int grow = (rl < 32) ? (c + 1) * 32 + rl : 256 + (c + 1) * 32 + (rl - 32);
                    cpa16(sb + W1STG_OFF + nbuf * 16384 + rl * 256 + (((uint32_t)cn ^ (rl & 7)) << 4),
                          W1Tn + (size_t)grow * EMB + cn * 8);
                }
                cpa_commit();
            }
            const int fbase = whi * 256 + c * 32;
            #pragma unroll
            for (int t = 0; t < 4; t++){
                int ng = fbase + t * 8 + 2 * (lane & 3);
                float2 bb = *(const float2*)(b1n + ng);
                float v0 = tanh_fast(acc[t][0] + bb.x);
                float v1 = tanh_fast(acc[t][1] + bb.y);
                float v2 = tanh_fast(acc[t][2] + bb.x);
                float v3 = tanh_fast(acc[t][3] + bb.y);
                afr[2*c + (t >> 1)][(t & 1) * 2 + 0] = f2h2(v0, v1);
                afr[2*c + (t >> 1)][(t & 1) * 2 + 1] = f2h2(v2, v3);
            }
            if (c + 1 < 8) cpa_wait0();
            __syncthreads();
        }
    }

    // ---- GEMM2: o = h @ W2T^T, 3-stage pipelined B (32KB chunks) ----
    {
        const __half* W2Tn = g_W2T + (size_t)n * W2PAD * MLPD;
        const float*  b2in = g_b2i + n * W2ROWS;

        uint32_t bA0[4], bA1[4];
        #pragma unroll
        for (int j2 = 0; j2 < 4; j2++){
            uint32_t base = sb + W2STG_OFF + bRowL * 1024 + bOff[j2] + (uint32_t)whi * 512u;
            bA0[j2] = base;
            bA1[j2] = base + 16 * 1024;
        }

        // prologue: preload chunk 0 -> buf0, chunk 1 -> buf1; wait chunk 0
        {
            #pragma unroll
            for (int i = 0; i < 8; i++){
                int lin = i * NTH + tid; int r = lin >> 6, cn = lin & 63;
                cpa16(sb + W2STG_OFF + r * 1024 + (((uint32_t)cn ^ (r & 7)) << 4),
                      W2Tn + (size_t)r * MLPD + cn * 8);
            }
            cpa_commit();
            #pragma unroll
            for (int i = 0; i < 8; i++){
                int lin = i * NTH + tid; int r = lin >> 6, cn = lin & 63;
                cpa16(sb + W2STG_OFF + 32768u + r * 1024 + (((uint32_t)cn ^ (r & 7)) << 4),
                      W2Tn + (size_t)(32 + r) * MLPD + cn * 8);
            }
            cpa_commit();
            cpa_wait1();   // chunk 0 resident; chunk 1 in flight
        }
        __syncthreads();

        const size_t scrb = (size_t)(b * N_BANDS + n) * 516;
        const int tok0 = t0 + wm * 16 + (lane >> 2);
        const uint32_t cmb = CMB_OFF + (uint32_t)wm * 2048u + (uint32_t)lane * 16u;

        uint32_t bufo  = 0;        // buffer of chunk c
        uint32_t ibufo = 65536u;   // buffer for chunk c+2
        #pragma unroll 1
        for (int c = 0; c < NCH2; c++){
            float acc[4][4];
            #pragma unroll
            for (int t = 0; t < 4; t++){ acc[t][0]=0.f; acc[t][1]=0.f; acc[t][2]=0.f; acc[t][3]=0.f; }
            #pragma unroll
            for (int j = 0; j < 16; j++){
                uint32_t ko = bufo + (uint32_t)(j >> 2) * 128u;
                uint32_t br0[4], br1[4];
                ldsm4(br0, bA0[j & 3] + ko);
                ldsm4(br1, bA1[j & 3] + ko);
                mma16816(acc[0], afr[j], br0[0], br0[1]);
                mma16816(acc[1], afr[j], br0[2], br0[3]);
                mma16816(acc[2], afr[j], br1[0], br1[1]);
                mma16816(acc[3], afr[j], br1[2], br1[3]);
            }
            // issue chunk c+2 into its buffer (read last at chunk c-1)
            if (c + 2 < NCH2){
                const __half* src = W2Tn + (size_t)(c + 2) * 32 * MLPD;
                #pragma unroll
                for (int i = 0; i < 8; i++){
                    int lin = i * NTH + tid; int r = lin >> 6, cn = lin & 63;
                    cpa16(sb + W2STG_OFF + ibufo + r * 1024 + (((uint32_t)cn ^ (r & 7)) << 4),
                          src + (size_t)r * MLPD + cn * 8);
                }
                cpa_commit();
            }
            if (whi){
                #pragma unroll
                for (int t = 0; t < 4; t++){
                    float4 v; v.x = acc[t][0]; v.y = acc[t][1]; v.z = acc[t][2]; v.w = acc[t][3];
                    *(float4*)(smem + cmb + t * 512) = v;
                }
            }
            __syncthreads();
            if (!whi){
                #pragma unroll
                for (int t = 0; t < 4; t++){
                    float4 v = *(const float4*)(smem + cmb + t * 512);
                    int jp = c * 16 + t * 4 + (lane & 3);
                    if (jp < 516){
                        float2 bb = *(const float2*)(b2in + 2 * jp);
                        float a0 = acc[t][0] + v.x + bb.x, g0 = acc[t][1] + v.y + bb.y;
                        float a1 = acc[t][2] + v.z + bb.x, g1 = acc[t][3] + v.w + bb.y;
                        float* dst = g_scr + (scrb + (size_t)jp) * TLEN + tok0;
                        dst[0] = a0 * sigm_fast(g0);
                        dst[8] = a1 * sigm_fast(g1);
                    }
                }
            }
            // ensure chunk c+1 is resident before next iteration
            if (c + 1 < NCH2){
                if (c + 2 < NCH2) cpa_wait1();
                else              cpa_wait0();
            }
            __syncthreads();
            bufo  += 32768u; if (bufo  == 98304u) bufo  = 0;
            ibufo += 32768u; if (ibufo == 98304u) ibufo = 0;
        }
    }
}

extern "C" void kernel_launch(void* const* d_in, const int* in_sizes, int n_in,
                              void* d_out, int out_size){
    const float* q        = (const float*)d_in[0];
    const float* ln_gamma = (const float*)d_in[1];
    const float* ln_beta  = (const float*)d_in[2];
    const float* W1       = (const float*)d_in[3];
    const float* b1       = (const float*)d_in[4];
    const float* W2       = (const float*)d_in[5];
    const float* b2       = (const float*)d_in[6];
    const float* fw       = (const float*)d_in[7];
    float* out = (float*)d_out;

    int B = in_sizes[0] / (N_BANDS * TLEN * EMB);

    prep_b2i<<<(N_BANDS * W2ROWS + 255) / 256, 256>>>(b2, fw);
    { dim3 g1(2, 8, N_BANDS);  prep_w1_t<<<g1, 256>>>(W1); }
    { dim3 g2(8, 17, N_BANDS); prep_w2_t<<<g2, 256>>>(W2, fw); }

    cudaFuncSetAttribute(omem_hmma_kernel, cudaFuncAttributeMaxDynamicSharedMemorySize, SMEM_TOTAL);
    dim3 grid(TLEN / TM, N_BANDS, B);
    omem_hmma_kernel<<<grid, NTH, SMEM_TOTAL>>>(q, ln_gamma, ln_beta, b1);

    {
        int total = B * 2 * NFREQ * TLEN;
        gather_kernel<<<(total + 255) / 256, 256>>>(out, B);
    }
}

// round 16
// speedup vs baseline: 1.1431x; 1.0363x over previous
#include <cuda_runtime.h>
#include <cuda_fp16.h>
#include <stdint.h>
#include <math.h>

#define N_BANDS 15
#define BW_     129
#define HOP_    64
#define NFREQ   1025
#define EMB     128
#define MLPD    512
#define TLEN    2048
#define TM      64
#define NTH     256
#define W2ROWS  1032
#define W2PAD   1056
#define NCH2    33

// smem layout (bytes) — 72KB total -> 2 CTAs/SM
#define AQN_OFF   0          // GEMM1: qn [64][256B] = 16384
#define W1STG_OFF 16384      // GEMM1: 2 x 16384
#define W2STG_OFF 0          // GEMM2: 2 x 32768 (aliases qn + W1 staging)
#define CMB_OFF   65536      // K-combine 8KB
#define SMEM_TOTAL 73728

__device__ __align__(16) __half g_W1T[(size_t)N_BANDS * MLPD * EMB];
__device__ __align__(16) __half g_W2T[(size_t)N_BANDS * W2PAD * MLPD];
__device__ float g_b2i[N_BANDS * W2ROWS];
__device__ float g_scr[(size_t)2 * N_BANDS * 516 * TLEN];

__device__ __forceinline__ uint32_t smem_u32(const void* p){
    uint32_t a;
    asm("{ .reg .u64 t; cvta.to.shared.u64 t, %1; cvt.u32.u64 %0, t; }" : "=r"(a) : "l"(p));
    return a;
}
__device__ __forceinline__ void ldsm4(uint32_t* r, uint32_t a){
    asm volatile("ldmatrix.sync.aligned.m8n8.x4.shared.b16 {%0,%1,%2,%3}, [%4];"
        : "=r"(r[0]),"=r"(r[1]),"=r"(r[2]),"=r"(r[3]) : "r"(a));
}
__device__ __forceinline__ void mma16816(float* c, const uint32_t* a, uint32_t b0, uint32_t b1){
    asm volatile("mma.sync.aligned.m16n8k16.row.col.f32.f16.f16.f32 "
        "{%0,%1,%2,%3}, {%4,%5,%6,%7}, {%8,%9}, {%0,%1,%2,%3};"
        : "+f"(c[0]),"+f"(c[1]),"+f"(c[2]),"+f"(c[3])
        : "r"(a[0]),"r"(a[1]),"r"(a[2]),"r"(a[3]),"r"(b0),"r"(b1));
}
__device__ __forceinline__ uint32_t f2h2(float a, float b){
    __half2 h = __floats2half2_rn(a, b);
    return *(uint32_t*)&h;
}
__device__ __forceinline__ void cpa16(uint32_t dst, const void* src){
    asm volatile("cp.async.cg.shared.global [%0], [%1], 16;" :: "r"(dst), "l"(src));
}
__device__ __forceinline__ void cpa_commit(){ asm volatile("cp.async.commit_group;" ::: "memory"); }
__device__ __forceinline__ void cpa_wait0(){ asm volatile("cp.async.wait_group 0;" ::: "memory"); }

__device__ __forceinline__ float tanh_fast(float x){
    x = fminf(fmaxf(x, -15.f), 15.f);
    float e = __expf(2.0f * x);
    return __fdividef(e - 1.0f, e + 1.0f);
}
__device__ __forceinline__ float sigm_fast(float g){
    return __fdividef(1.0f, 1.0f + __expf(-g));
}

// ---------------- prep kernels ----------------
__global__ void prep_b2i(const float* __restrict__ b2, const float* __restrict__ fw){
    int idx = blockIdx.x * blockDim.x + threadIdx.x;
    if (idx >= N_BANDS * W2ROWS) return;
    int r = idx % W2ROWS, n = idx / W2ROWS;
    int j = r >> 1, gbit = r & 1;
    float v = b2[(size_t)n * W2ROWS + (gbit ? j + 516 : j)];
    if (!gbit){
        int cc = j >= 258; int rem = j - cc * 258;
        v *= fw[n * BW_ + (rem >> 1)];
    }
    g_b2i[idx] = v;
}

__global__ void prep_w1_t(const float* __restrict__ W1){
    __shared__ float s[64][65];
    const int n = blockIdx.z, f0 = blockIdx.y * 64, e0 = blockIdx.x * 64;
    const int tid = threadIdx.x;
    const int i0 = tid >> 6, j = tid & 63;
    const float* src = W1 + ((size_t)n * EMB + e0) * MLPD + f0;
    #pragma unroll
    for (int p = 0; p < 16; p++){
        int i = p * 4 + i0;
        s[i][j] = src[(size_t)i * MLPD + j];
    }
    __syncthreads();
    __half* dst = g_W1T + ((size_t)n * MLPD + f0) * EMB + e0;
    #pragma unroll
    for (int p = 0; p < 16; p++){
        int jj = p * 4 + i0;
        dst[(size_t)jj * EMB + j] = __float2half(s[j][jj]);
    }
}

__global__ void prep_w2_t(const float* __restrict__ W2, const float* __restrict__ fw){
    __shared__ float sa[64][33], sg[64][33];
    const int n = blockIdx.z, j0 = blockIdx.y * 32, k0 = blockIdx.x * 64;
    const int tid = threadIdx.x;
    const int kk0 = tid >> 5, jj = tid & 31;
    const float* src = W2 + (size_t)n * MLPD * W2ROWS + (size_t)k0 * W2ROWS;
    const int jf_l = j0 + jj;
    #pragma unroll
    for (int p = 0; p < 8; p++){
        int kk = p * 8 + kk0;
        float va = 0.f, vg = 0.f;
        if (jf_l < 516){
            va = src[(size_t)kk * W2ROWS + jf_l];
            vg = src[(size_t)kk * W2ROWS + 516 + jf_l];
        }
        sa[kk][jj] = va; sg[kk][jj] = vg;
    }
    __syncthreads();
    const int w = tid >> 5, kk2 = tid & 31;
    #pragma unroll
    for (int p = 0; p < 8; p++){
        int rl = p * 8 + w;
        int jj2 = rl >> 1, g = rl & 1;
        int jf = j0 + jj2;
        int r = 2 * jf + g;
        if (r < W2PAD){
            float v0, v1;
            if (g){ v0 = sg[2*kk2][jj2]; v1 = sg[2*kk2+1][jj2]; }
            else {
                v0 = sa[2*kk2][jj2]; v1 = sa[2*kk2+1][jj2];
                if (jf < 516){
                    int cc = jf >= 258; int rem = jf - cc * 258;
                    float fwv = fw[n * BW_ + (rem >> 1)];
                    v0 *= fwv; v1 *= fwv;
                }
            }
            *(__half2*)(g_W2T + ((size_t)n * W2PAD + r) * MLPD + k0 + 2 * kk2) =
                __floats2half2_rn(v0, v1);
        }
    }
}

// ---------------- gather: 2 t's per thread, streaming loads ----------------
__global__ void gather_kernel(float* __restrict__ out, int B){
    int idx = blockIdx.x * blockDim.x + threadIdx.x;
    int total = B * 2 * NFREQ * (TLEN / 2);
    if (idx >= total) return;
    int t2   = idx & (TLEN / 2 - 1);
    int rest = idx >> 10;
    int freq = rest % NFREQ;
    int rest2 = rest / NFREQ;
    int c = rest2 & 1;
    int b = rest2 >> 1;
    int t = t2 * 2;
    int n_lo = (freq >= 128) ? ((freq - 128 + 63) >> 6) : 0;
    int n_hi = freq >> 6; if (n_hi > 14) n_hi = 14;
    float s0x = 0.f, s0y = 0.f, s1x = 0.f, s1y = 0.f;
    for (int n = n_lo; n <= n_hi; n++){
        int f = freq - (n << 6);
        const float* base = g_scr + (((size_t)(b * N_BANDS + n) * 516) + (size_t)(c * 258 + 2 * f)) * TLEN + t;
        float2 r0 = __ldcs((const float2*)base);          // re: t, t+1
        float2 r1 = __ldcs((const float2*)(base + TLEN)); // im: t, t+1
        s0x += r0.x; s0y += r1.x;
        s1x += r0.y; s1y += r1.y;
    }
    float4 v; v.x = s0x; v.y = s0y; v.z = s1x; v.w = s1y;
    ((float4*)out)[idx] = v;
}

// ---------------- main kernel ----------------
__global__ __launch_bounds__(NTH, 2)
void omem_hmma_kernel(const float* __restrict__ q,
                      const float* __restrict__ ln_gamma,
                      const float* __restrict__ ln_beta,
                      const float* __restrict__ b1){
    extern __shared__ __align__(1024) char smem[];
    const uint32_t sb = smem_u32(smem);
    const int tid = threadIdx.x, warp = tid >> 5, lane = tid & 31;
    const int wm = warp & 3, whi = warp >> 2;
    const int b = blockIdx.z, n = blockIdx.y, t0 = blockIdx.x * TM;

    const __half* W1Tn = g_W1T + (size_t)n * MLPD * EMB;

    // prefetch W1 feature-chunk 0 before LN
    {
        #pragma unroll
        for (int i = 0; i < 4; i++){
            int lin = i * NTH + tid; int rl = lin >> 4, cn = lin & 15;
            int grow = (rl < 32) ? rl : 256 + (rl - 32);
            cpa16(sb + W1STG_OFF + rl * 256 + (((uint32_t)cn ^ (rl & 7)) << 4),
                  W1Tn + (size_t)grow * EMB + cn * 8);
        }
        cpa_commit();
    }

    // ---- LayerNorm -> qn fp16, swizzled [64][256B] ----
    {
        const float* qb = q + ((size_t)(b * N_BANDS + n) * TLEN + t0) * EMB;
        float4 gg  = ((const float4*)(ln_gamma + (size_t)n * EMB))[lane];
        float4 bet = ((const float4*)(ln_beta  + (size_t)n * EMB))[lane];
        for (int i = warp; i < TM; i += 8){
            float4 v = ((const float4*)(qb + (size_t)i * EMB))[lane];
            float s  = v.x + v.y + v.z + v.w;
            float s2 = v.x*v.x + v.y*v.y + v.z*v.z + v.w*v.w;
            #pragma unroll
            for (int off = 16; off; off >>= 1){
                s  += __shfl_xor_sync(0xffffffffu, s,  off);
                s2 += __shfl_xor_sync(0xffffffffu, s2, off);
            }
            float mu = s * (1.0f/EMB);
            float var = s2 * (1.0f/EMB) - mu*mu;
            float rs = rsqrtf(var + 1e-5f);
            uint2 pk;
            pk.x = f2h2((v.x - mu)*rs*gg.x + bet.x, (v.y - mu)*rs*gg.y + bet.y);
            pk.y = f2h2((v.z - mu)*rs*gg.z + bet.z, (v.w - mu)*rs*gg.w + bet.w);
            uint32_t ch = (uint32_t)(lane >> 1) ^ (uint32_t)(i & 7);
            *(uint2*)(smem + AQN_OFF + i * 256 + ch * 16 + (lane & 1) * 8) = pk;
        }
    }

    const uint32_t aRow = wm * 16 + (lane & 15);
    const uint32_t aS   = aRow & 7;
    const uint32_t aHi  = lane >> 4;
    const uint32_t bRowL = (lane & 7) | ((lane & 16) >> 1);
    const uint32_t bHi   = (lane >> 3) & 1;
    const uint32_t bS    = bRowL & 7;

    uint32_t aOff[4], bOff[4];
    #pragma unroll
    for (int j2 = 0; j2 < 4; j2++){
        aOff[j2] = (((2u*j2 + aHi) ^ aS) << 4);
        bOff[j2] = (((2u*j2 + bHi) ^ bS) << 4);
    }

    cpa_wait0();
    __syncthreads();

    uint32_t afr[16][4];

    // ---- GEMM1 (fused): 16 token-rows x 256 features per warp ----
    {
        const float* b1n = b1 + (size_t)n * MLPD;
        uint32_t aA[4];
        #pragma unroll
        for (int j2 = 0; j2 < 4; j2++) aA[j2] = sb + AQN_OFF + aRow * 256 + aOff[j2];
        #pragma unroll 1
        for (int c = 0; c < 8; c++){
            const int cbuf = c & 1, nbuf = (c + 1) & 1;
            float acc[4][4];
            #pragma unroll
            for (int t = 0; t < 4; t++){ acc[t][0]=0.f; acc[t][1]=0.f; acc[t][2]=0.f; acc[t][3]=0.f; }
            uint32_t bB[4];
            #pragma unroll
            for (int j2 = 0; j2 < 4; j2++)
                bB[j2] = sb + W1STG_OFF + cbuf * 16384 + (whi * 32 + bRowL) * 256 + bOff[j2];
            #pragma unroll
            for (int ks = 0; ks < 8; ks++){
                uint32_t ko = (uint32_t)(ks >> 2) * 128u;
                uint32_t a[4], br0[4], br1[4];
                ldsm4(a,   aA[ks & 3] + ko);
                ldsm4(br0, bB[ks & 3] + ko);
                ldsm4(br1, bB[ks & 3] + ko + 16 * 256);
                mma16816(acc[0], a, br0[0], br0[1]);
                mma16816(acc[1], a, br0[2], br0[3]);
                mma16816(acc[2], a, br1[0], br1[1]);
                mma16816(acc[3], a, br1[2], br1[3]);
            }
            if (c + 1 < 8){
                #pragma unroll
                for (int i = 0; i < 4; i++){
                    int lin = i * NTH + tid; int rl = lin >> 4, cn = lin & 15;
                    int grow = (rl < 32) ? (c + 1) * 32 + rl : 256 + (c + 1) * 32 + (rl - 32);
                    cpa16(sb + W1STG_OFF + nbuf * 16384 + rl * 256 + (((uint32_t)cn ^ (rl & 7)) << 4),
                          W1Tn + (size_t)grow * EMB + cn * 8);
                }
                cpa_commit();
            }
            const int fbase = whi * 256 + c * 32;
            #pragma unroll
            for (int t = 0; t < 4; t++){
                int ng = fbase + t * 8 + 2 * (lane & 3);
                float2 bb = *(const float2*)(b1n + ng);
                float v0 = tanh_fast(acc[t][0] + bb.x);
                float v1 = tanh_fast(acc[t][1] + bb.y);
                float v2 = tanh_fast(acc[t][2] + bb.x);
                float v3 = tanh_fast(acc[t][3] + bb.y);
                afr[2*c + (t >> 1)][(t & 1) * 2 + 0] = f2h2(v0, v1);
                afr[2*c + (t >> 1)][(t & 1) * 2 + 1] = f2h2(v2, v3);
            }
            if (c + 1 < 8) cpa_wait0();
            __syncthreads();
        }
    }

    // ---- GEMM2: o = h @ W2T^T, double-buffered B, symmetric epilogue split ----
    {
        const __half* W2Tn = g_W2T + (size_t)n * W2PAD * MLPD;
        const float*  b2in = g_b2i + n * W2ROWS;

        uint32_t bA0[4], bA1[4];
        #pragma unroll
        for (int j2 = 0; j2 < 4; j2++){
            uint32_t base = sb + W2STG_OFF + bRowL * 1024 + bOff[j2] + (uint32_t)whi * 512u;
            bA0[j2] = base;
            bA1[j2] = base + 16 * 1024;
        }

        // preload chunk 0 into buf 0
        {
            #pragma unroll
            for (int i = 0; i < 8; i++){
                int lin = i * NTH + tid; int r = lin >> 6, cn = lin & 63;
                cpa16(sb + W2STG_OFF + r * 1024 + (((uint32_t)cn ^ (r & 7)) << 4),
                      W2Tn + (size_t)r * MLPD + cn * 8);
            }
            cpa_commit();
            cpa_wait0();
        }
        __syncthreads();

        const size_t scrb = (size_t)(b * N_BANDS + n) * 516;
        const int tok0 = t0 + wm * 16 + (lane >> 2);
        // combine slots: [wm][side(whi of storer)][tile(2)][lane] float4 -> 8KB
        const uint32_t cmbSt = CMB_OFF + (uint32_t)wm * 2048u + (uint32_t)whi * 1024u + (uint32_t)lane * 16u;
        const uint32_t cmbLd = CMB_OFF + (uint32_t)wm * 2048u + (uint32_t)(whi ^ 1) * 1024u + (uint32_t)lane * 16u;
        const int tOwn = whi * 2;     // tiles this warp epilogues
        const int tSt  = 2 - tOwn;    // tiles this warp publishes (partner's)

        #pragma unroll 1
        for (int c = 0; c < NCH2; c++){
            const uint32_t bufo = (uint32_t)(c & 1) * 32768u;
            float acc[4][4];
            #pragma unroll
            for (int t = 0; t < 4; t++){ acc[t][0]=0.f; acc[t][1]=0.f; acc[t][2]=0.f; acc[t][3]=0.f; }
            #pragma unroll
            for (int j = 0; j < 16; j++){
                uint32_t ko = bufo + (uint32_t)(j >> 2) * 128u;
                uint32_t br0[4], br1[4];
                ldsm4(br0, bA0[j & 3] + ko);
                ldsm4(br1, bA1[j & 3] + ko);
                mma16816(acc[0], afr[j], br0[0], br0[1]);
                mma16816(acc[1], afr[j], br0[2], br0[3]);
                mma16816(acc[2], afr[j], br1[0], br1[1]);
                mma16816(acc[3], afr[j], br1[2], br1[3]);
            }
            // prefetch next chunk into other buffer
            if (c + 1 < NCH2){
                const __half* src = W2Tn + (size_t)(c + 1) * 32 * MLPD;
                const uint32_t nbufo = (uint32_t)((c + 1) & 1) * 32768u;
                #pragma unroll
                for (int i = 0; i < 8; i++){
                    int lin = i * NTH + tid; int r = lin >> 6, cn = lin & 63;
                    cpa16(sb + W2STG_OFF + nbufo + r * 1024 + (((uint32_t)cn ^ (r & 7)) << 4),
                          src + (size_t)r * MLPD + cn * 8);
                }
                cpa_commit();
            }
            // publish partner's 2 tiles
            #pragma unroll
            for (int t = 0; t < 2; t++){
                float4 v;
                v.x = acc[tSt + t][0]; v.y = acc[tSt + t][1];
                v.z = acc[tSt + t][2]; v.w = acc[tSt + t][3];
                *(float4*)(smem + cmbSt + t * 512) = v;
            }
            __syncthreads();
            // epilogue: own 2 tiles (both halves work)
            #pragma unroll
            for (int t = 0; t < 2; t++){
                float4 v = *(const float4*)(smem + cmbLd + t * 512);
                int tt = tOwn + t;
                int jp = c * 16 + tt * 4 + (lane & 3);
                if (jp < 516){
                    float2 bb = *(const float2*)(b2in + 2 * jp);
                    float a0 = acc[tt][0] + v.x + bb.x, g0 = acc[tt][1] + v.y + bb.y;
                    float a1 = acc[tt][2] + v.z + bb.x, g1 = acc[tt][3] + v.w + bb.y;
                    float* dst = g_scr + (scrb + (size_t)jp) * TLEN + tok0;
                    dst[0] = a0 * sigm_fast(g0);
                    dst[8] = a1 * sigm_fast(g1);
                }
            }
            if (c + 1 < NCH2) cpa_wait0();
            __syncthreads();
        }
    }
}

extern "C" void kernel_launch(void* const* d_in, const int* in_sizes, int n_in,
                              void* d_out, int out_size){
    const float* q        = (const float*)d_in[0];
    const float* ln_gamma = (const float*)d_in[1];
    const float* ln_beta  = (const float*)d_in[2];
    const float* W1       = (const float*)d_in[3];
    const float* b1       = (const float*)d_in[4];
    const float* W2       = (const float*)d_in[5];
    const float* b2       = (const float*)d_in[6];
    const float* fw       = (const float*)d_in[7];
    float* out = (float*)d_out;

    int B = in_sizes[0] / (N_BANDS * TLEN * EMB);

    prep_b2i<<<(N_BANDS * W2ROWS + 255) / 256, 256>>>(b2, fw);
    { dim3 g1(2, 8, N_BANDS);  prep_w1_t<<<g1, 256>>>(W1); }
    { dim3 g2(8, 17, N_BANDS); prep_w2_t<<<g2, 256>>>(W2, fw); }

    cudaFuncSetAttribute(omem_hmma_kernel, cudaFuncAttributeMaxDynamicSharedMemorySize, SMEM_TOTAL);
    dim3 grid(TLEN / TM, N_BANDS, B);
    omem_hmma_kernel<<<grid, NTH, SMEM_TOTAL>>>(q, ln_gamma, ln_beta, b1);

    {
        int total = B * 2 * NFREQ * (TLEN / 2);
        gather_kernel<<<(total + 255) / 256, 256>>>(out, B);
    }
}

// round 17
// speedup vs baseline: 1.1658x; 1.0199x over previous
#include <cuda_runtime.h>
#include <cuda_fp16.h>
#include <stdint.h>
#include <math.h>

#define N_BANDS 15
#define BW_     129
#define HOP_    64
#define NFREQ   1025
#define EMB     128
#define MLPD    512
#define TLEN    2048
#define TM      64
#define NTH     256
#define W2ROWS  1032
#define W2PAD   1056
#define NCH2    33

// smem layout (bytes) — 72KB total -> 2 CTAs/SM
#define AQN_OFF   0          // GEMM1: qn [64][256B] = 16384
#define W1STG_OFF 16384      // GEMM1: 2 x 16384
#define W2STG_OFF 0          // GEMM2: 2 x 32768 (aliases qn + W1 staging)
#define CMB_OFF   65536      // K-combine 8KB
#define SMEM_TOTAL 73728

__device__ __align__(16) __half g_W1T[(size_t)N_BANDS * MLPD * EMB];
__device__ __align__(16) __half g_W2T[(size_t)N_BANDS * W2PAD * MLPD];
__device__ float g_b2i[N_BANDS * W2ROWS];
__device__ float g_scr[(size_t)2 * N_BANDS * 516 * TLEN];

__device__ __forceinline__ uint32_t smem_u32(const void* p){
    uint32_t a;
    asm("{ .reg .u64 t; cvta.to.shared.u64 t, %1; cvt.u32.u64 %0, t; }" : "=r"(a) : "l"(p));
    return a;
}
__device__ __forceinline__ void ldsm4(uint32_t* r, uint32_t a){
    asm volatile("ldmatrix.sync.aligned.m8n8.x4.shared.b16 {%0,%1,%2,%3}, [%4];"
        : "=r"(r[0]),"=r"(r[1]),"=r"(r[2]),"=r"(r[3]) : "r"(a));
}
__device__ __forceinline__ void mma16816(float* c, const uint32_t* a, uint32_t b0, uint32_t b1){
    asm volatile("mma.sync.aligned.m16n8k16.row.col.f32.f16.f16.f32 "
        "{%0,%1,%2,%3}, {%4,%5,%6,%7}, {%8,%9}, {%0,%1,%2,%3};"
        : "+f"(c[0]),"+f"(c[1]),"+f"(c[2]),"+f"(c[3])
        : "r"(a[0]),"r"(a[1]),"r"(a[2]),"r"(a[3]),"r"(b0),"r"(b1));
}
__device__ __forceinline__ uint32_t f2h2(float a, float b){
    __half2 h = __floats2half2_rn(a, b);
    return *(uint32_t*)&h;
}
__device__ __forceinline__ void cpa16(uint32_t dst, const void* src){
    asm volatile("cp.async.cg.shared.global [%0], [%1], 16;" :: "r"(dst), "l"(src));
}
__device__ __forceinline__ void cpa_commit(){ asm volatile("cp.async.commit_group;" ::: "memory"); }
__device__ __forceinline__ void cpa_wait0(){ asm volatile("cp.async.wait_group 0;" ::: "memory"); }

__device__ __forceinline__ float tanh_fast(float x){
    x = fminf(fmaxf(x, -15.f), 15.f);
    float e = __expf(2.0f * x);
    return __fdividef(e - 1.0f, e + 1.0f);
}
__device__ __forceinline__ float sigm_fast(float g){
    return __fdividef(1.0f, 1.0f + __expf(-g));
}

// ---------------- prep kernels ----------------
__global__ void prep_b2i(const float* __restrict__ b2, const float* __restrict__ fw){
    int idx = blockIdx.x * blockDim.x + threadIdx.x;
    if (idx >= N_BANDS * W2ROWS) return;
    int r = idx % W2ROWS, n = idx / W2ROWS;
    int j = r >> 1, gbit = r & 1;
    float v = b2[(size_t)n * W2ROWS + (gbit ? j + 516 : j)];
    if (!gbit){
        int cc = j >= 258; int rem = j - cc * 258;
        v *= fw[n * BW_ + (rem >> 1)];
    }
    g_b2i[idx] = v;
}

__global__ void prep_w1_t(const float* __restrict__ W1){
    __shared__ float s[64][65];
    const int n = blockIdx.z, f0 = blockIdx.y * 64, e0 = blockIdx.x * 64;
    const int tid = threadIdx.x;
    const int i0 = tid >> 6, j = tid & 63;
    const float* src = W1 + ((size_t)n * EMB + e0) * MLPD + f0;
    #pragma unroll
    for (int p = 0; p < 16; p++){
        int i = p * 4 + i0;
        s[i][j] = src[(size_t)i * MLPD + j];
    }
    __syncthreads();
    __half* dst = g_W1T + ((size_t)n * MLPD + f0) * EMB + e0;
    #pragma unroll
    for (int p = 0; p < 16; p++){
        int jj = p * 4 + i0;
        dst[(size_t)jj * EMB + j] = __float2half(s[j][jj]);
    }
}

__global__ void prep_w2_t(const float* __restrict__ W2, const float* __restrict__ fw){
    __shared__ float sa[64][33], sg[64][33];
    const int n = blockIdx.z, j0 = blockIdx.y * 32, k0 = blockIdx.x * 64;
    const int tid = threadIdx.x;
    const int kk0 = tid >> 5, jj = tid & 31;
    const float* src = W2 + (size_t)n * MLPD * W2ROWS + (size_t)k0 * W2ROWS;
    const int jf_l = j0 + jj;
    #pragma unroll
    for (int p = 0; p < 8; p++){
        int kk = p * 8 + kk0;
        float va = 0.f, vg = 0.f;
        if (jf_l < 516){
            va = src[(size_t)kk * W2ROWS + jf_l];
            vg = src[(size_t)kk * W2ROWS + 516 + jf_l];
        }
        sa[kk][jj] = va; sg[kk][jj] = vg;
    }
    __syncthreads();
    const int w = tid >> 5, kk2 = tid & 31;
    #pragma unroll
    for (int p = 0; p < 8; p++){
        int rl = p * 8 + w;
        int jj2 = rl >> 1, g = rl & 1;
        int jf = j0 + jj2;
        int r = 2 * jf + g;
        if (r < W2PAD){
            float v0, v1;
            if (g){ v0 = sg[2*kk2][jj2]; v1 = sg[2*kk2+1][jj2]; }
            else {
                v0 = sa[2*kk2][jj2]; v1 = sa[2*kk2+1][jj2];
                if (jf < 516){
                    int cc = jf >= 258; int rem = jf - cc * 258;
                    float fwv = fw[n * BW_ + (rem >> 1)];
                    v0 *= fwv; v1 *= fwv;
                }
            }
            *(__half2*)(g_W2T + ((size_t)n * W2PAD + r) * MLPD + k0 + 2 * kk2) =
                __floats2half2_rn(v0, v1);
        }
    }
}

// ---------------- gather: 2 t's per thread, streaming loads ----------------
__global__ void gather_kernel(float* __restrict__ out, int B){
    int idx = blockIdx.x * blockDim.x + threadIdx.x;
    int total = B * 2 * NFREQ * (TLEN / 2);
    if (idx >= total) return;
    int t2   = idx & (TLEN / 2 - 1);
    int rest = idx >> 10;
    int freq = rest % NFREQ;
    int rest2 = rest / NFREQ;
    int c = rest2 & 1;
    int b = rest2 >> 1;
    int t = t2 * 2;
    int n_lo = (freq >= 128) ? ((freq - 128 + 63) >> 6) : 0;
    int n_hi = freq >> 6; if (n_hi > 14) n_hi = 14;
    float s0x = 0.f, s0y = 0.f, s1x = 0.f, s1y = 0.f;
    for (int n = n_lo; n <= n_hi; n++){
        int f = freq - (n << 6);
        const float* base = g_scr + (((size_t)(b * N_BANDS + n) * 516) + (size_t)(c * 258 + 2 * f)) * TLEN + t;
        float2 r0 = __ldcs((const float2*)base);          // re: t, t+1
        float2 r1 = __ldcs((const float2*)(base + TLEN)); // im: t, t+1
        s0x += r0.x; s0y += r1.x;
        s1x += r0.y; s1y += r1.y;
    }
    float4 v; v.x = s0x; v.y = s0y; v.z = s1x; v.w = s1y;
    ((float4*)out)[idx] = v;
}

// ---------------- main kernel (R12 structure) ----------------
__global__ __launch_bounds__(NTH, 2)
void omem_hmma_kernel(const float* __restrict__ q,
                      const float* __restrict__ ln_gamma,
                      const float* __restrict__ ln_beta,
                      const float* __restrict__ b1){
    extern __shared__ __align__(1024) char smem[];
    const uint32_t sb = smem_u32(smem);
    const int tid = threadIdx.x, warp = tid >> 5, lane = tid & 31;
    const int wm = warp & 3, whi = warp >> 2;
    const int b = blockIdx.z, n = blockIdx.y, t0 = blockIdx.x * TM;

    const __half* W1Tn = g_W1T + (size_t)n * MLPD * EMB;

    // prefetch W1 feature-chunk 0 before LN
    {
        #pragma unroll
        for (int i = 0; i < 4; i++){
            int lin = i * NTH + tid; int rl = lin >> 4, cn = lin & 15;
            int grow = (rl < 32) ? rl : 256 + (rl - 32);
            cpa16(sb + W1STG_OFF + rl * 256 + (((uint32_t)cn ^ (rl & 7)) << 4),
                  W1Tn + (size_t)grow * EMB + cn * 8);
        }
        cpa_commit();
    }

    // ---- LayerNorm -> qn fp16, swizzled [64][256B] ----
    {
        const float* qb = q + ((size_t)(b * N_BANDS + n) * TLEN + t0) * EMB;
        float4 gg  = ((const float4*)(ln_gamma + (size_t)n * EMB))[lane];
        float4 bet = ((const float4*)(ln_beta  + (size_t)n * EMB))[lane];
        for (int i = warp; i < TM; i += 8){
            float4 v = ((const float4*)(qb + (size_t)i * EMB))[lane];
            float s  = v.x + v.y + v.z + v.w;
            float s2 = v.x*v.x + v.y*v.y + v.z*v.z + v.w*v.w;
            #pragma unroll
            for (int off = 16; off; off >>= 1){
                s  += __shfl_xor_sync(0xffffffffu, s,  off);
                s2 += __shfl_xor_sync(0xffffffffu, s2, off);
            }
            float mu = s * (1.0f/EMB);
            float var = s2 * (1.0f/EMB) - mu*mu;
            float rs = rsqrtf(var + 1e-5f);
            uint2 pk;
            pk.x = f2h2((v.x - mu)*rs*gg.x + bet.x, (v.y - mu)*rs*gg.y + bet.y);
            pk.y = f2h2((v.z - mu)*rs*gg.z + bet.z, (v.w - mu)*rs*gg.w + bet.w);
            uint32_t ch = (uint32_t)(lane >> 1) ^ (uint32_t)(i & 7);
            *(uint2*)(smem + AQN_OFF + i * 256 + ch * 16 + (lane & 1) * 8) = pk;
        }
    }

    const uint32_t aRow = wm * 16 + (lane & 15);
    const uint32_t aS   = aRow & 7;
    const uint32_t aHi  = lane >> 4;
    const uint32_t bRowL = (lane & 7) | ((lane & 16) >> 1);
    const uint32_t bHi   = (lane >> 3) & 1;
    const uint32_t bS    = bRowL & 7;

    uint32_t aOff[4], bOff[4];
    #pragma unroll
    for (int j2 = 0; j2 < 4; j2++){
        aOff[j2] = (((2u*j2 + aHi) ^ aS) << 4);
        bOff[j2] = (((2u*j2 + bHi) ^ bS) << 4);
    }

    cpa_wait0();
    __syncthreads();

    uint32_t afr[16][4];

    // ---- GEMM1 (fused): 16 token-rows x 256 features per warp ----
    {
        const float* b1n = b1 + (size_t)n * MLPD;
        uint32_t aA[4];
        #pragma unroll
        for (int j2 = 0; j2 < 4; j2++) aA[j2] = sb + AQN_OFF + aRow * 256 + aOff[j2];
        #pragma unroll 1
        for (int c = 0; c < 8; c++){
            const int cbuf = c & 1, nbuf = (c + 1) & 1;
            float acc[4][4];
            #pragma unroll
            for (int t = 0; t < 4; t++){ acc[t][0]=0.f; acc[t][1]=0.f; acc[t][2]=0.f; acc[t][3]=0.f; }
            uint32_t bB[4];
            #pragma unroll
            for (int j2 = 0; j2 < 4; j2++)
                bB[j2] = sb + W1STG_OFF + cbuf * 16384 + (whi * 32 + bRowL) * 256 + bOff[j2];
            #pragma unroll
            for (int ks = 0; ks < 8; ks++){
                uint32_t ko = (uint32_t)(ks >> 2) * 128u;
                uint32_t a[4], br0[4], br1[4];
                ldsm4(a,   aA[ks & 3] + ko);
                ldsm4(br0, bB[ks & 3] + ko);
                ldsm4(br1, bB[ks & 3] + ko + 16 * 256);
                mma16816(acc[0], a, br0[0], br0[1]);
                mma16816(acc[1], a, br0[2], br0[3]);
                mma16816(acc[2], a, br1[0], br1[1]);
                mma16816(acc[3], a, br1[2], br1[3]);
            }
            if (c + 1 < 8){
                #pragma unroll
                for (int i = 0; i < 4; i++){
                    int lin = i * NTH + tid; int rl = lin >> 4, cn = lin & 15;
                    int grow = (rl < 32) ? (c + 1) * 32 + rl : 256 + (c + 1) * 32 + (rl - 32);
                    cpa16(sb + W1STG_OFF + nbuf * 16384 + rl * 256 + (((uint32_t)cn ^ (rl & 7)) << 4),
                          W1Tn + (size_t)grow * EMB + cn * 8);
                }
                cpa_commit();
            }
            const int fbase = whi * 256 + c * 32;
            #pragma unroll
            for (int t = 0; t < 4; t++){
                int ng = fbase + t * 8 + 2 * (lane & 3);
                float2 bb = *(const float2*)(b1n + ng);
                float v0 = tanh_fast(acc[t][0] + bb.x);
                float v1 = tanh_fast(acc[t][1] + bb.y);
                float v2 = tanh_fast(acc[t][2] + bb.x);
                float v3 = tanh_fast(acc[t][3] + bb.y);
                afr[2*c + (t >> 1)][(t & 1) * 2 + 0] = f2h2(v0, v1);
                afr[2*c + (t >> 1)][(t & 1) * 2 + 1] = f2h2(v2, v3);
            }
            if (c + 1 < 8) cpa_wait0();
            __syncthreads();
        }
    }

    // ---- GEMM2: o = h @ W2T^T, double-buffered B (R12 epilogue) ----
    {
        const __half* W2Tn = g_W2T + (size_t)n * W2PAD * MLPD;
        const float*  b2in = g_b2i + n * W2ROWS;

        uint32_t bA0[4], bA1[4];
        #pragma unroll
        for (int j2 = 0; j2 < 4; j2++){
            uint32_t base = sb + W2STG_OFF + bRowL * 1024 + bOff[j2] + (uint32_t)whi * 512u;
            bA0[j2] = base;
            bA1[j2] = base + 16 * 1024;
        }

        // preload chunk 0 into buf 0
        {
            #pragma unroll
            for (int i = 0; i < 8; i++){
                int lin = i * NTH + tid; int r = lin >> 6, cn = lin & 63;
                cpa16(sb + W2STG_OFF + r * 1024 + (((uint32_t)cn ^ (r & 7)) << 4),
                      W2Tn + (size_t)r * MLPD + cn * 8);
            }
            cpa_commit();
            cpa_wait0();
        }
        __syncthreads();

        const size_t scrb = (size_t)(b * N_BANDS + n) * 516;
        const int tok0 = t0 + wm * 16 + (lane >> 2);
        const uint32_t cmb = CMB_OFF + (uint32_t)wm * 2048u + (uint32_t)lane * 16u;

        #pragma unroll 1
        for (int c = 0; c < NCH2; c++){
            const uint32_t bufo = (uint32_t)(c & 1) * 32768u;
            float acc[4][4];
            #pragma unroll
            for (int t = 0; t < 4; t++){ acc[t][0]=0.f; acc[t][1]=0.f; acc[t][2]=0.f; acc[t][3]=0.f; }
            #pragma unroll
            for (int j = 0; j < 16; j++){
                uint32_t ko = bufo + (uint32_t)(j >> 2) * 128u;
                uint32_t br0[4], br1[4];
                ldsm4(br0, bA0[j & 3] + ko);
                ldsm4(br1, bA1[j & 3] + ko);
                mma16816(acc[0], afr[j], br0[0], br0[1]);
                mma16816(acc[1], afr[j], br0[2], br0[3]);
                mma16816(acc[2], afr[j], br1[0], br1[1]);
                mma16816(acc[3], afr[j], br1[2], br1[3]);
            }
            // prefetch next chunk into other buffer (barrier-free w/ double buffer)
            if (c + 1 < NCH2){
                const __half* src = W2Tn + (size_t)(c + 1) * 32 * MLPD;
                const uint32_t nbufo = (uint32_t)((c + 1) & 1) * 32768u;
                #pragma unroll
                for (int i = 0; i < 8; i++){
                    int lin = i * NTH + tid; int r = lin >> 6, cn = lin & 63;
                    cpa16(sb + W2STG_OFF + nbufo + r * 1024 + (((uint32_t)cn ^ (r & 7)) << 4),
                          src + (size_t)r * MLPD + cn * 8);
                }
                cpa_commit();
            }
            if (whi){
                #pragma unroll
                for (int t = 0; t < 4; t++){
                    float4 v; v.x = acc[t][0]; v.y = acc[t][1]; v.z = acc[t][2]; v.w = acc[t][3];
                    *(float4*)(smem + cmb + t * 512) = v;
                }
            }
            __syncthreads();
            if (!whi){
                #pragma unroll
                for (int t = 0; t < 4; t++){
                    float4 v = *(const float4*)(smem + cmb + t * 512);
                    int jp = c * 16 + t * 4 + (lane & 3);
                    if (jp < 516){
                        float2 bb = *(const float2*)(b2in + 2 * jp);
                        float a0 = acc[t][0] + v.x + bb.x, g0 = acc[t][1] + v.y + bb.y;
                        float a1 = acc[t][2] + v.z + bb.x, g1 = acc[t][3] + v.w + bb.y;
                        float* dst = g_scr + (scrb + (size_t)jp) * TLEN + tok0;
                        dst[0] = a0 * sigm_fast(g0);
                        dst[8] = a1 * sigm_fast(g1);
                    }
                }
            }
            if (c + 1 < NCH2) cpa_wait0();
            __syncthreads();
        }
    }
}

extern "C" void kernel_launch(void* const* d_in, const int* in_sizes, int n_in,
                              void* d_out, int out_size){
    const float* q        = (const float*)d_in[0];
    const float* ln_gamma = (const float*)d_in[1];
    const float* ln_beta  = (const float*)d_in[2];
    const float* W1       = (const float*)d_in[3];
    const float* b1       = (const float*)d_in[4];
    const float* W2       = (const float*)d_in[5];
    const float* b2       = (const float*)d_in[6];
    const float* fw       = (const float*)d_in[7];
    float* out = (float*)d_out;

    int B = in_sizes[0] / (N_BANDS * TLEN * EMB);

    prep_b2i<<<(N_BANDS * W2ROWS + 255) / 256, 256>>>(b2, fw);
    { dim3 g1(2, 8, N_BANDS);  prep_w1_t<<<g1, 256>>>(W1); }
    { dim3 g2(8, 17, N_BANDS); prep_w2_t<<<g2, 256>>>(W2, fw); }

    cudaFuncSetAttribute(omem_hmma_kernel, cudaFuncAttributeMaxDynamicSharedMemorySize, SMEM_TOTAL);
    dim3 grid(TLEN / TM, N_BANDS, B);
    omem_hmma_kernel<<<grid, NTH, SMEM_TOTAL>>>(q, ln_gamma, ln_beta, b1);

    {
        int total = B * 2 * NFREQ * (TLEN / 2);
        gather_kernel<<<(total + 255) / 256, 256>>>(out, B);
    }
}